// round 1
// baseline (speedup 1.0000x reference)
#include <cuda_runtime.h>
#include <math.h>

// Problem constants (fixed by dataset)
#define NXD   512          // design points
#define MDIM  514          // number of B-spline basis functions = NXD + 2 (k=3)
#define NEV   8192         // eval bins
#define NROWS 256          // 8*32 rows
#define SREG  1e-3

// ---------------------------------------------------------------------------
// Compile-time tables: design basis, BtB band, banded Cholesky, pre-scaled
// substitution coefficients. All in double, stored as float.
// ---------------------------------------------------------------------------
struct Tables {
    // forward solve:  y[j] = bd[j]*b[j] - f1[j]*y[j-1] - f2[j]*y[j-2] - f3[j]*y[j-3]
    float bd[MDIM], f1[MDIM], f2[MDIM], f3[MDIM];
    // backward solve: c[j] = bd[j]*y[j] - g1[j]*c[j+1] - g2[j]*c[j+2] - g3[j]*c[j+3]
    float g1[MDIM], g2[MDIM], g3[MDIM];
    // design-point basis weights (base index = min(p,510))
    float dw[NXD][4];
};

constexpr double cx(int i) { return -1.0 + 2.0 * (double)i / 511.0; }
constexpr double cknot(int i) {
    int j = i - 3;
    if (j < 0) j = 0;
    if (j > 511) j = 511;
    return cx(j);
}
constexpr double csqrt(double v) {
    double g = v < 1.0 ? 1.0 : v;
    for (int it = 0; it < 40; ++it) g = 0.5 * (g + v / g);
    return g;
}

constexpr Tables make_tables() {
    Tables T{};
    // --- design basis via Cox-de Boor (local, 4 nonzeros per point) ---
    double dwd[NXD][4] = {};
    for (int p = 0; p < NXD; ++p) {
        int base = p < 510 ? p : 510;
        int i = base + 3;              // knot interval index: t[i] <= x < t[i+1]
        double x = cx(p);
        double N[4] = {1, 0, 0, 0};
        double left[4] = {}, right[4] = {};
        for (int j = 1; j <= 3; ++j) {
            left[j]  = x - cknot(i + 1 - j);
            right[j] = cknot(i + j) - x;
            double saved = 0;
            for (int r = 0; r < j; ++r) {
                double temp = N[r] / (right[r + 1] + left[j - r]);
                N[r]  = saved + right[r + 1] * temp;
                saved = left[j - r] * temp;
            }
            N[j] = saved;
        }
        for (int a = 0; a < 4; ++a) { dwd[p][a] = N[a]; T.dw[p][a] = (float)N[a]; }
    }
    // --- BtB band: band[d][r] = BtB[r][r+d], d=0..3 ---
    double band[4][MDIM] = {};
    for (int p = 0; p < NXD; ++p) {
        int base = p < 510 ? p : 510;
        for (int a = 0; a < 4; ++a)
            for (int b = a; b < 4; ++b)
                band[b - a][base + a] += dwd[p][a] * dwd[p][b];
    }
    for (int r = 0; r < MDIM; ++r) band[0][r] += SREG;
    // --- banded Cholesky (lower, bandwidth 3): Lk[i] = L[i][i-k] ---
    double Ld[MDIM] = {}, L1a[MDIM] = {}, L2a[MDIM] = {}, L3a[MDIM] = {};
    for (int i = 0; i < MDIM; ++i) {
        double l3 = 0, l2 = 0, l1 = 0;
        if (i >= 3) l3 = band[3][i - 3] / Ld[i - 3];
        if (i >= 2) {
            double s = band[2][i - 2];
            if (i >= 3) s -= l3 * L1a[i - 2];
            l2 = s / Ld[i - 2];
        }
        if (i >= 1) {
            double s = band[1][i - 1];
            if (i >= 2) s -= l2 * L1a[i - 1];
            if (i >= 3) s -= l3 * L2a[i - 1];
            l1 = s / Ld[i - 1];
        }
        double s = band[0][i] - l1 * l1 - l2 * l2 - l3 * l3;
        Ld[i] = csqrt(s);
        L1a[i] = l1; L2a[i] = l2; L3a[i] = l3;
    }
    // --- pre-scaled substitution coefficients ---
    for (int j = 0; j < MDIM; ++j) {
        double dinv = 1.0 / Ld[j];
        T.bd[j] = (float)dinv;
        T.f1[j] = (float)(L1a[j] * dinv);
        T.f2[j] = (float)(L2a[j] * dinv);
        T.f3[j] = (float)(L3a[j] * dinv);
        T.g1[j] = (float)((j + 1 < MDIM ? L1a[j + 1] : 0.0) * dinv);
        T.g2[j] = (float)((j + 2 < MDIM ? L2a[j + 2] : 0.0) * dinv);
        T.g3[j] = (float)((j + 3 < MDIM ? L3a[j + 3] : 0.0) * dinv);
    }
    return T;
}

__device__ const Tables g_tab = make_tables();

// ---------------------------------------------------------------------------
// Scratch (device globals; no allocation allowed)
// ---------------------------------------------------------------------------
__device__ float  g_btz[MDIM][NROWS];    // Btz, transposed: [basis][row]
__device__ float  g_coef[MDIM][NROWS];   // y then coef, transposed
__device__ float4 g_ew[NEV];             // eval basis weights
__device__ int    g_ebase[NEV];          // eval base index

// ---------------------------------------------------------------------------
// K0: eval-point basis (De Boor in double)
// ---------------------------------------------------------------------------
__device__ __forceinline__ double dknot(int i) {
    int j = i - 3;
    j = j < 0 ? 0 : (j > 511 ? 511 : j);
    return -1.0 + 2.0 * (double)j / 511.0;
}

__global__ void k_ebasis() {
    int e = blockIdx.x * blockDim.x + threadIdx.x;
    if (e >= NEV) return;
    float xf = (float)(-1.0 + 2.0 * (double)e / 8191.0);
    double x = (double)xf;
    int idx = (int)floor((x + 1.0) * (511.0 / 2.0));
    if (idx < 0) idx = 0;
    if (idx > 510) idx = 510;
    int i = idx + 3;
    double N[4] = {1, 0, 0, 0};
    double left[4], right[4];
#pragma unroll
    for (int j = 1; j <= 3; ++j) {
        left[j]  = x - dknot(i + 1 - j);
        right[j] = dknot(i + j) - x;
        double saved = 0;
#pragma unroll
        for (int r = 0; r < 3; ++r) {
            if (r < j) {
                double temp = N[r] / (right[r + 1] + left[j - r]);
                N[r]  = saved + right[r + 1] * temp;
                saved = left[j - r] * temp;
            }
        }
        N[j] = saved;
    }
    g_ebase[e] = idx;
    g_ew[e] = make_float4((float)N[0], (float)N[1], (float)N[2], (float)N[3]);
}

// ---------------------------------------------------------------------------
// K1: Btz = bx^T Z per row (stored transposed for the solver)
// ---------------------------------------------------------------------------
__global__ void k_btz(const float* __restrict__ Z) {
    int row = blockIdx.x;
    __shared__ float zs[NXD];
    for (int p = threadIdx.x; p < NXD; p += blockDim.x)
        zs[p] = Z[row * NXD + p];
    __syncthreads();
    for (int j = threadIdx.x; j < MDIM; j += blockDim.x) {
        float s = 0.f;
        int plo = j - 3 < 0 ? 0 : j - 3;
        int phi = j < 511 ? j : 511;
        for (int p = plo; p <= phi; ++p) {
            int base = p < 510 ? p : 510;
            int a = j - base;
            if (a >= 0 && a < 4) s += g_tab.dw[p][a] * zs[p];
        }
        g_btz[j][row] = s;
    }
}

// ---------------------------------------------------------------------------
// K2: banded Cholesky solve, one thread per row (forward + backward)
// ---------------------------------------------------------------------------
__global__ void k_solve() {
    int r = blockIdx.x * blockDim.x + threadIdx.x;
    if (r >= NROWS) return;
    float y1 = 0.f, y2 = 0.f, y3 = 0.f;
#pragma unroll 8
    for (int j = 0; j < MDIM; ++j) {
        float acc = g_btz[j][r] * g_tab.bd[j];
        acc = fmaf(-g_tab.f2[j], y2, acc);
        acc = fmaf(-g_tab.f3[j], y3, acc);
        float y = fmaf(-g_tab.f1[j], y1, acc);   // only op on the serial chain
        g_coef[j][r] = y;
        y3 = y2; y2 = y1; y1 = y;
    }
    float c1 = 0.f, c2 = 0.f, c3 = 0.f;
#pragma unroll 8
    for (int j = MDIM - 1; j >= 0; --j) {
        float acc = g_coef[j][r] * g_tab.bd[j];
        acc = fmaf(-g_tab.g2[j], c2, acc);
        acc = fmaf(-g_tab.g3[j], c3, acc);
        float c = fmaf(-g_tab.g1[j], c1, acc);
        g_coef[j][r] = c;
        c3 = c2; c2 = c1; c1 = c;
    }
}

// ---------------------------------------------------------------------------
// K3: evaluation  out[row][e] = sum_a w[e][a] * coef[base_e+a][row]
// grid (NEV/256 e-chunks, NROWS/16 row groups); block of 256 threads along e
// ---------------------------------------------------------------------------
__global__ void k_eval(float* __restrict__ out) {
    int e = blockIdx.x * blockDim.x + threadIdx.x;
    int rbase = blockIdx.y * 16;
    float4 w = g_ew[e];
    int b = g_ebase[e];
#pragma unroll
    for (int rr = 0; rr < 16; ++rr) {
        int row = rbase + rr;
        float v = w.x * g_coef[b][row];
        v = fmaf(w.y, g_coef[b + 1][row], v);
        v = fmaf(w.z, g_coef[b + 2][row], v);
        v = fmaf(w.w, g_coef[b + 3][row], v);
        out[row * NEV + e] = v;
    }
}

// ---------------------------------------------------------------------------
extern "C" void kernel_launch(void* const* d_in, const int* in_sizes, int n_in,
                              void* d_out, int out_size) {
    const float* Z = (const float*)d_in[0];
    float* out = (float*)d_out;
    k_ebasis<<<NEV / 256, 256>>>();
    k_btz<<<NROWS, 256>>>(Z);
    k_solve<<<8, 32>>>();
    k_eval<<<dim3(NEV / 256, NROWS / 16), 256>>>(out);
}

// round 2
// speedup vs baseline: 3.7012x; 3.7012x over previous
#include <cuda_runtime.h>
#include <math.h>

// Problem constants (fixed by dataset)
#define NXD   512          // design points
#define MDIM  514          // number of basis functions = NXD + 2 (k=3)
#define NEV   8192         // eval bins
#define NROWS 256          // 8*32 rows
#define SREG  1e-3

// ---------------------------------------------------------------------------
// Compile-time tables: design basis, BtB band, banded Cholesky, pre-scaled
// substitution coefficients. All in double, stored as float.
// ---------------------------------------------------------------------------
struct Tables {
    float bd[MDIM], f1[MDIM], f2[MDIM], f3[MDIM];
    float g1[MDIM], g2[MDIM], g3[MDIM];
    float dw[NXD][4];
};

constexpr double cx(int i) { return -1.0 + 2.0 * (double)i / 511.0; }
constexpr double cknot(int i) {
    int j = i - 3;
    if (j < 0) j = 0;
    if (j > 511) j = 511;
    return cx(j);
}
constexpr double csqrt(double v) {
    double g = v < 1.0 ? 1.0 : v;
    for (int it = 0; it < 40; ++it) g = 0.5 * (g + v / g);
    return g;
}

constexpr Tables make_tables() {
    Tables T{};
    double dwd[NXD][4] = {};
    for (int p = 0; p < NXD; ++p) {
        int base = p < 510 ? p : 510;
        int i = base + 3;
        double x = cx(p);
        double N[4] = {1, 0, 0, 0};
        double left[4] = {}, right[4] = {};
        for (int j = 1; j <= 3; ++j) {
            left[j]  = x - cknot(i + 1 - j);
            right[j] = cknot(i + j) - x;
            double saved = 0;
            for (int r = 0; r < j; ++r) {
                double temp = N[r] / (right[r + 1] + left[j - r]);
                N[r]  = saved + right[r + 1] * temp;
                saved = left[j - r] * temp;
            }
            N[j] = saved;
        }
        for (int a = 0; a < 4; ++a) { dwd[p][a] = N[a]; T.dw[p][a] = (float)N[a]; }
    }
    double band[4][MDIM] = {};
    for (int p = 0; p < NXD; ++p) {
        int base = p < 510 ? p : 510;
        for (int a = 0; a < 4; ++a)
            for (int b = a; b < 4; ++b)
                band[b - a][base + a] += dwd[p][a] * dwd[p][b];
    }
    for (int r = 0; r < MDIM; ++r) band[0][r] += SREG;
    double Ld[MDIM] = {}, L1a[MDIM] = {}, L2a[MDIM] = {}, L3a[MDIM] = {};
    for (int i = 0; i < MDIM; ++i) {
        double l3 = 0, l2 = 0, l1 = 0;
        if (i >= 3) l3 = band[3][i - 3] / Ld[i - 3];
        if (i >= 2) {
            double s = band[2][i - 2];
            if (i >= 3) s -= l3 * L1a[i - 2];
            l2 = s / Ld[i - 2];
        }
        if (i >= 1) {
            double s = band[1][i - 1];
            if (i >= 2) s -= l2 * L1a[i - 1];
            if (i >= 3) s -= l3 * L2a[i - 1];
            l1 = s / Ld[i - 1];
        }
        double s = band[0][i] - l1 * l1 - l2 * l2 - l3 * l3;
        Ld[i] = csqrt(s);
        L1a[i] = l1; L2a[i] = l2; L3a[i] = l3;
    }
    for (int j = 0; j < MDIM; ++j) {
        double dinv = 1.0 / Ld[j];
        T.bd[j] = (float)dinv;
        T.f1[j] = (float)(L1a[j] * dinv);
        T.f2[j] = (float)(L2a[j] * dinv);
        T.f3[j] = (float)(L3a[j] * dinv);
        T.g1[j] = (float)((j + 1 < MDIM ? L1a[j + 1] : 0.0) * dinv);
        T.g2[j] = (float)((j + 2 < MDIM ? L2a[j + 2] : 0.0) * dinv);
        T.g3[j] = (float)((j + 3 < MDIM ? L3a[j + 3] : 0.0) * dinv);
    }
    return T;
}

__device__ const Tables g_tab = make_tables();

// Scratch (device globals; allocation is forbidden)
__device__ float  g_coef[MDIM][NROWS];   // solved coefficients, transposed
__device__ float4 g_ew[NEV];             // eval basis weights
__device__ int    g_ebase[NEV];          // eval base index

// ---------------------------------------------------------------------------
// K0: eval-point basis (De Boor in double)
// ---------------------------------------------------------------------------
__device__ __forceinline__ double dknot(int i) {
    int j = i - 3;
    j = j < 0 ? 0 : (j > 511 ? 511 : j);
    return -1.0 + 2.0 * (double)j / 511.0;
}

__global__ void k_ebasis() {
    int e = blockIdx.x * blockDim.x + threadIdx.x;
    if (e >= NEV) return;
    float xf = (float)(-1.0 + 2.0 * (double)e / 8191.0);
    double x = (double)xf;
    int idx = (int)floor((x + 1.0) * (511.0 / 2.0));
    if (idx < 0) idx = 0;
    if (idx > 510) idx = 510;
    int i = idx + 3;
    double N[4] = {1, 0, 0, 0};
    double left[4], right[4];
#pragma unroll
    for (int j = 1; j <= 3; ++j) {
        left[j]  = x - dknot(i + 1 - j);
        right[j] = dknot(i + j) - x;
        double saved = 0;
#pragma unroll
        for (int r = 0; r < 3; ++r) {
            if (r < j) {
                double temp = N[r] / (right[r + 1] + left[j - r]);
                N[r]  = saved + right[r + 1] * temp;
                saved = left[j - r] * temp;
            }
        }
        N[j] = saved;
    }
    g_ebase[e] = idx;
    g_ew[e] = make_float4((float)N[0], (float)N[1], (float)N[2], (float)N[3]);
}

// ---------------------------------------------------------------------------
// K1 (fused): Btz + banded Cholesky solve, all intermediate state in SMEM.
// 32 blocks x 256 threads, 8 rows per block.
// ---------------------------------------------------------------------------
#define RPB 8
#define BSTRIDE 9   // padded row stride for s_btz (kills bank conflicts)

__global__ void k_fit(const float* __restrict__ Z) {
    __shared__ float s_btz[MDIM * BSTRIDE];
    __shared__ float s_tab[7][MDIM];
    int tid = threadIdx.x;
    int rowbase = blockIdx.x * RPB;

    // Stage substitution tables into shared
    for (int i = tid; i < MDIM; i += 256) {
        s_tab[0][i] = g_tab.bd[i];
        s_tab[1][i] = g_tab.f1[i];
        s_tab[2][i] = g_tab.f2[i];
        s_tab[3][i] = g_tab.f3[i];
        s_tab[4][i] = g_tab.g1[i];
        s_tab[5][i] = g_tab.g2[i];
        s_tab[6][i] = g_tab.g3[i];
    }

    // Btz: one warp per row, lanes stripe over j
    int w = tid >> 5, lane = tid & 31;
    const float* zr = Z + (size_t)(rowbase + w) * NXD;
    for (int j = lane; j < MDIM; j += 32) {
        float s = 0.f;
        int plo = j - 3 < 0 ? 0 : j - 3;
        int phi = j < 511 ? j : 511;
        for (int p = plo; p <= phi; ++p) {
            int base = p < 510 ? p : 510;
            int a = j - base;
            if (a >= 0 && a < 4) s += g_tab.dw[p][a] * __ldg(zr + p);
        }
        s_btz[j * BSTRIDE + w] = s;
    }
    __syncthreads();

    // Solve: one thread per row, everything from SMEM
    if (tid < RPB) {
        int r = tid;
        float y1 = 0.f, y2 = 0.f, y3 = 0.f;
#pragma unroll 8
        for (int j = 0; j < MDIM; ++j) {
            float acc = s_btz[j * BSTRIDE + r] * s_tab[0][j];
            acc = fmaf(-s_tab[2][j], y2, acc);
            acc = fmaf(-s_tab[3][j], y3, acc);
            float y = fmaf(-s_tab[1][j], y1, acc);
            s_btz[j * BSTRIDE + r] = y;
            y3 = y2; y2 = y1; y1 = y;
        }
        float c1 = 0.f, c2 = 0.f, c3 = 0.f;
#pragma unroll 8
        for (int j = MDIM - 1; j >= 0; --j) {
            float acc = s_btz[j * BSTRIDE + r] * s_tab[0][j];
            acc = fmaf(-s_tab[5][j], c2, acc);
            acc = fmaf(-s_tab[6][j], c3, acc);
            float c = fmaf(-s_tab[4][j], c1, acc);
            s_btz[j * BSTRIDE + r] = c;
            c3 = c2; c2 = c1; c1 = c;
        }
    }
    __syncthreads();

    // Write coefficients out (transposed layout for eval)
    for (int idx = tid; idx < MDIM * RPB; idx += 256) {
        int j = idx / RPB, r = idx % RPB;
        g_coef[j][rowbase + r] = s_btz[j * BSTRIDE + r];
    }
}

// ---------------------------------------------------------------------------
// K2: evaluation with shared coef slab + float4 stores.
// grid (NEV/512, NROWS/16), block 128 threads, 4 e's per thread.
// ---------------------------------------------------------------------------
#define EPB   512
#define RPB2  16
#define JWIN  40   // max j-window per block: 512*511/8192 ~ 32, +3, padded

__device__ __forceinline__ float ev4(float4 w, int o,
                                     float c0, float c1, float c2,
                                     float c3, float c4) {
    float a0 = o ? c1 : c0;
    float a1 = o ? c2 : c1;
    float a2 = o ? c3 : c2;
    float a3 = o ? c4 : c3;
    float v = w.x * a0;
    v = fmaf(w.y, a1, v);
    v = fmaf(w.z, a2, v);
    v = fmaf(w.w, a3, v);
    return v;
}

__global__ void k_eval(float* __restrict__ out) {
    __shared__ float s_coef[JWIN * RPB2];
    int tid = threadIdx.x;
    int e0 = blockIdx.x * EPB;
    int rbase = blockIdx.y * RPB2;
    int j0 = g_ebase[e0];

    // Stage the coef window
    for (int idx = tid; idx < JWIN * RPB2; idx += 128) {
        int jl = idx >> 4, r = idx & 15;
        int j = j0 + jl;
        if (j > MDIM - 1) j = MDIM - 1;
        s_coef[idx] = g_coef[j][rbase + r];
    }
    __syncthreads();

    int e = e0 + tid * 4;
    float4 w0 = g_ew[e], w1 = g_ew[e + 1], w2 = g_ew[e + 2], w3 = g_ew[e + 3];
    int b0 = g_ebase[e] - j0;
    int o1 = g_ebase[e + 1] - j0 - b0;
    int o2 = g_ebase[e + 2] - j0 - b0;
    int o3 = g_ebase[e + 3] - j0 - b0;

    float4* outv = (float4*)(out + e);
#pragma unroll 4
    for (int rr = 0; rr < RPB2; ++rr) {
        int row = rbase + rr;
        const float* cp = &s_coef[b0 * RPB2 + rr];
        float c0 = cp[0 * RPB2];
        float c1 = cp[1 * RPB2];
        float c2 = cp[2 * RPB2];
        float c3 = cp[3 * RPB2];
        float c4 = cp[4 * RPB2];
        float4 v;
        v.x = w0.x * c0;
        v.x = fmaf(w0.y, c1, v.x);
        v.x = fmaf(w0.z, c2, v.x);
        v.x = fmaf(w0.w, c3, v.x);
        v.y = ev4(w1, o1, c0, c1, c2, c3, c4);
        v.z = ev4(w2, o2, c0, c1, c2, c3, c4);
        v.w = ev4(w3, o3, c0, c1, c2, c3, c4);
        outv[(size_t)row * (NEV / 4)] = v;
    }
}

// ---------------------------------------------------------------------------
extern "C" void kernel_launch(void* const* d_in, const int* in_sizes, int n_in,
                              void* d_out, int out_size) {
    const float* Z = (const float*)d_in[0];
    float* out = (float*)d_out;
    k_ebasis<<<NEV / 256, 256>>>();
    k_fit<<<NROWS / RPB, 256>>>(Z);
    k_eval<<<dim3(NEV / EPB, NROWS / RPB2), 128>>>(out);
}

// round 3
// speedup vs baseline: 3.9441x; 1.0656x over previous
#include <cuda_runtime.h>
#include <math.h>

// Problem constants (fixed by dataset)
#define NXD   512          // design points
#define MDIM  514          // number of basis functions = NXD + 2 (k=3)
#define NEV   8192         // eval bins
#define NROWS 256          // 8*32 rows
#define SREG  1e-3

#define W     48           // A^-1 band half-width (decay^48 << fp32 eps)
#define NTAP  (2*W + 1)    // 97
#define AROW  100          // padded row stride for g_ainv (16B aligned)

// ---------------------------------------------------------------------------
// Compile-time tables: design basis + pre-scaled banded-Cholesky coefficients.
// ---------------------------------------------------------------------------
struct Tables {
    float bd[MDIM], f1[MDIM], f2[MDIM], f3[MDIM];   // forward subst
    float g1[MDIM], g2[MDIM], g3[MDIM];             // backward subst
    float dw[NXD][4];                               // design basis weights
};

constexpr double cx(int i) { return -1.0 + 2.0 * (double)i / 511.0; }
constexpr double cknot(int i) {
    int j = i - 3;
    if (j < 0) j = 0;
    if (j > 511) j = 511;
    return cx(j);
}
constexpr double csqrt(double v) {
    double g = v < 1.0 ? 1.0 : v;
    for (int it = 0; it < 40; ++it) g = 0.5 * (g + v / g);
    return g;
}

constexpr Tables make_tables() {
    Tables T{};
    double dwd[NXD][4] = {};
    for (int p = 0; p < NXD; ++p) {
        int base = p < 510 ? p : 510;
        int i = base + 3;
        double x = cx(p);
        double N[4] = {1, 0, 0, 0};
        double left[4] = {}, right[4] = {};
        for (int j = 1; j <= 3; ++j) {
            left[j]  = x - cknot(i + 1 - j);
            right[j] = cknot(i + j) - x;
            double saved = 0;
            for (int r = 0; r < j; ++r) {
                double temp = N[r] / (right[r + 1] + left[j - r]);
                N[r]  = saved + right[r + 1] * temp;
                saved = left[j - r] * temp;
            }
            N[j] = saved;
        }
        for (int a = 0; a < 4; ++a) { dwd[p][a] = N[a]; T.dw[p][a] = (float)N[a]; }
    }
    double band[4][MDIM] = {};
    for (int p = 0; p < NXD; ++p) {
        int base = p < 510 ? p : 510;
        for (int a = 0; a < 4; ++a)
            for (int b = a; b < 4; ++b)
                band[b - a][base + a] += dwd[p][a] * dwd[p][b];
    }
    for (int r = 0; r < MDIM; ++r) band[0][r] += SREG;
    double Ld[MDIM] = {}, L1a[MDIM] = {}, L2a[MDIM] = {}, L3a[MDIM] = {};
    for (int i = 0; i < MDIM; ++i) {
        double l3 = 0, l2 = 0, l1 = 0;
        if (i >= 3) l3 = band[3][i - 3] / Ld[i - 3];
        if (i >= 2) {
            double s = band[2][i - 2];
            if (i >= 3) s -= l3 * L1a[i - 2];
            l2 = s / Ld[i - 2];
        }
        if (i >= 1) {
            double s = band[1][i - 1];
            if (i >= 2) s -= l2 * L1a[i - 1];
            if (i >= 3) s -= l3 * L2a[i - 1];
            l1 = s / Ld[i - 1];
        }
        double s = band[0][i] - l1 * l1 - l2 * l2 - l3 * l3;
        Ld[i] = csqrt(s);
        L1a[i] = l1; L2a[i] = l2; L3a[i] = l3;
    }
    for (int j = 0; j < MDIM; ++j) {
        double dinv = 1.0 / Ld[j];
        T.bd[j] = (float)dinv;
        T.f1[j] = (float)(L1a[j] * dinv);
        T.f2[j] = (float)(L2a[j] * dinv);
        T.f3[j] = (float)(L3a[j] * dinv);
        T.g1[j] = (float)((j + 1 < MDIM ? L1a[j + 1] : 0.0) * dinv);
        T.g2[j] = (float)((j + 2 < MDIM ? L2a[j + 2] : 0.0) * dinv);
        T.g3[j] = (float)((j + 3 < MDIM ? L3a[j + 3] : 0.0) * dinv);
    }
    return T;
}

__device__ const Tables g_tab = make_tables();

// Scratch (device globals; allocation is forbidden)
__device__ float g_btz[MDIM][NROWS];     // B^T z, transposed
__device__ float g_ainv[MDIM][AROW];     // truncated A^-1 band, row i: taps i-W..i+W

// ---------------------------------------------------------------------------
// K1: blocks 0..15 -> Btz (16 rows each); blocks 16..32 -> A^-1 band prep.
// ---------------------------------------------------------------------------
__global__ void __launch_bounds__(512) k1(const float* __restrict__ Z) {
    int b = blockIdx.x;
    int tid = threadIdx.x;

    if (b < 16) {
        // ---- Btz for rows b*16 .. b*16+15 ----
        __shared__ float s_z[16][513];   // padded: bank = (r+p) mod 32, conflict-free
        int rowbase = b * 16;
        for (int idx = tid; idx < 16 * 512; idx += 512) {
            int r = idx >> 9, p = idx & 511;
            s_z[r][p] = Z[(size_t)(rowbase + r) * NXD + p];
        }
        __syncthreads();

        int w = tid >> 5, lane = tid & 31;
        int r = lane & 15, jg = lane >> 4;
#pragma unroll 1
        for (int s = 0; s < 17; ++s) {
            int j = w + 16 * jg + 32 * s;
            if (j >= MDIM) break;
            float acc = 0.f;
            int plo = j - 3 < 0 ? 0 : j - 3;
            int phi = j < 511 ? j : 511;
            for (int p = plo; p <= phi; ++p) {
                int base = p < 510 ? p : 510;
                int a = j - base;
                if (a >= 0 && a < 4) acc += g_tab.dw[p][a] * s_z[r][p];
            }
            g_btz[j][rowbase + r] = acc;
        }
    } else {
        // ---- A^-1 band: column i, truncated to i +/- W ----
        int i = (b - 16) * 32 + tid;
        if (tid < 32 && i < MDIM) {
            float y[W + 1];
#pragma unroll
            for (int d = 0; d <= W; ++d) {
                int j = i + d;
                float v = 0.f;
                if (j < MDIM) {
                    if (d == 0) v = g_tab.bd[i];
                    else {
                        v = -g_tab.f1[j] * y[d - 1];
                        if (d >= 2) v = fmaf(-g_tab.f2[j], y[d - 2], v);
                        if (d >= 3) v = fmaf(-g_tab.f3[j], y[d - 3], v);
                    }
                }
                y[d] = v;
            }
            float c1 = 0.f, c2 = 0.f, c3 = 0.f;
#pragma unroll
            for (int dd = 0; dd <= 2 * W; ++dd) {
                int j = i + W - dd;
                float c = 0.f;
                if (j >= 0 && j < MDIM) {
                    float yv = (dd <= W) ? y[W - dd] : 0.f;
                    c = g_tab.bd[j] * yv;
                    c = fmaf(-g_tab.g1[j], c1, c);
                    c = fmaf(-g_tab.g2[j], c2, c);
                    c = fmaf(-g_tab.g3[j], c3, c);
                }
                g_ainv[i][2 * W - dd] = c;
                c3 = c2; c2 = c1; c1 = c;
            }
        }
    }
}

// ---------------------------------------------------------------------------
// K2: fused coef (banded A^-1 matvec) + spline evaluation.
// grid (16 e-chunks of 512, 16 row-chunks of 16), 128 threads.
// ---------------------------------------------------------------------------
#define EPB   512
#define RPB   16
#define JWIN  40                 // coef j-window per block
#define BWIN  (JWIN + 2 * W)     // 136 btz values needed

__device__ __forceinline__ float kf(int i) {
    int j = i - 3;
    j = j < 0 ? 0 : (j > 511 ? 511 : j);
    return (float)(-1.0 + 2.0 * (double)j / 511.0);
}

__device__ __forceinline__ int ebase_of(int e) {
    double x = -1.0 + 2.0 * (double)e / 8191.0;
    float xf = (float)x;
    int id = (int)floor(((double)xf + 1.0) * 255.5);
    return id < 0 ? 0 : (id > 510 ? 510 : id);
}

__device__ __forceinline__ void ewts(int e, float4& wout, int& idx) {
    float x = (float)(-1.0 + 2.0 * (double)e / 8191.0);
    int id = (int)floor(((double)x + 1.0) * 255.5);
    id = id < 0 ? 0 : (id > 510 ? 510 : id);
    int i = id + 3;
    float N[4] = {1.f, 0.f, 0.f, 0.f};
    float left[4], right[4];
#pragma unroll
    for (int j = 1; j <= 3; ++j) {
        left[j]  = x - kf(i + 1 - j);
        right[j] = kf(i + j) - x;
        float saved = 0.f;
#pragma unroll
        for (int r = 0; r < 3; ++r) {
            if (r < j) {
                float temp = __fdividef(N[r], right[r + 1] + left[j - r]);
                N[r]  = fmaf(right[r + 1], temp, saved);
                saved = left[j - r] * temp;
            }
        }
        N[j] = saved;
    }
    idx = id;
    wout = make_float4(N[0], N[1], N[2], N[3]);
}

__device__ __forceinline__ float ev4(float4 w, int o,
                                     float c0, float c1, float c2,
                                     float c3, float c4) {
    float a0 = o ? c1 : c0;
    float a1 = o ? c2 : c1;
    float a2 = o ? c3 : c2;
    float a3 = o ? c4 : c3;
    float v = w.x * a0;
    v = fmaf(w.y, a1, v);
    v = fmaf(w.z, a2, v);
    v = fmaf(w.w, a3, v);
    return v;
}

__global__ void __launch_bounds__(128) k2(float* __restrict__ out) {
    __shared__ float s_b[BWIN][RPB];      // btz window
    __shared__ float s_coef[JWIN][RPB];   // local coefficients
    int tid = threadIdx.x;
    int e0 = blockIdx.x * EPB;
    int rbase = blockIdx.y * RPB;
    int j0 = ebase_of(e0);
    int jb = j0 - W;

    // Stage btz window (zeros outside the valid range)
    for (int idx = tid; idx < BWIN * RPB; idx += 128) {
        int jl = idx >> 4, r = idx & 15;
        int j = jb + jl;
        s_b[jl][r] = (j >= 0 && j < MDIM) ? g_btz[j][rbase + r] : 0.f;
    }
    __syncthreads();

    // Coef: 40 j x 16 r per block, 97-tap dots against A^-1 band
    {
        int jl0 = tid >> 4, r = tid & 15;
#pragma unroll 1
        for (int jj = jl0; jj < JWIN; jj += 8) {
            int j = j0 + jj;
            float acc = 0.f;
            if (j < MDIM) {
                const float* av = g_ainv[j];
#pragma unroll 4
                for (int t = 0; t < NTAP; ++t)
                    acc = fmaf(__ldg(av + t), s_b[jj + t][r], acc);
            }
            s_coef[jj][r] = acc;
        }
    }
    __syncthreads();

    // Eval: 4 consecutive e per thread, float4 stores
    int e = e0 + tid * 4;
    float4 w0, w1, w2, w3;
    int i0, i1, i2, i3;
    ewts(e,     w0, i0);
    ewts(e + 1, w1, i1);
    ewts(e + 2, w2, i2);
    ewts(e + 3, w3, i3);
    int b0 = i0 - j0;
    int o1 = i1 - i0;
    int o2 = i2 - i0;
    int o3 = i3 - i0;

    float4* outv = (float4*)(out + e);
#pragma unroll 4
    for (int rr = 0; rr < RPB; ++rr) {
        int row = rbase + rr;
        const float* cp = &s_coef[b0][rr];
        float c0 = cp[0 * RPB];
        float c1 = cp[1 * RPB];
        float c2 = cp[2 * RPB];
        float c3 = cp[3 * RPB];
        float c4 = cp[4 * RPB];
        float4 v;
        v.x = w0.x * c0;
        v.x = fmaf(w0.y, c1, v.x);
        v.x = fmaf(w0.z, c2, v.x);
        v.x = fmaf(w0.w, c3, v.x);
        v.y = ev4(w1, o1, c0, c1, c2, c3, c4);
        v.z = ev4(w2, o2, c0, c1, c2, c3, c4);
        v.w = ev4(w3, o3, c0, c1, c2, c3, c4);
        outv[(size_t)row * (NEV / 4)] = v;
    }
}

// ---------------------------------------------------------------------------
extern "C" void kernel_launch(void* const* d_in, const int* in_sizes, int n_in,
                              void* d_out, int out_size) {
    const float* Z = (const float*)d_in[0];
    float* out = (float*)d_out;
    k1<<<33, 512>>>(Z);
    k2<<<dim3(NEV / EPB, NROWS / RPB), 128>>>(out);
}

// round 4
// speedup vs baseline: 5.8833x; 1.4917x over previous
#include <cuda_runtime.h>
#include <math.h>

// Problem constants (fixed by dataset)
#define NXD   512          // design points
#define MDIM  514          // number of basis functions = NXD + 2 (k=3)
#define NEV   8192         // eval bins
#define NROWS 256          // 8*32 rows
#define SREG  1e-3

#define W     48           // A^-1 band half-width (decay^48 << fp32 eps)
#define NTAP  (2*W + 1)    // 97
#define AROW  100          // padded row stride for g_ainv

// ---------------------------------------------------------------------------
// Compile-time tables: design basis + pre-scaled banded-Cholesky coefficients.
// ---------------------------------------------------------------------------
struct Tables {
    float bd[MDIM], f1[MDIM], f2[MDIM], f3[MDIM];   // forward subst
    float g1[MDIM], g2[MDIM], g3[MDIM];             // backward subst
    float dw[NXD][4];                               // design basis weights
};

constexpr double cx(int i) { return -1.0 + 2.0 * (double)i / 511.0; }
constexpr double cknot(int i) {
    int j = i - 3;
    if (j < 0) j = 0;
    if (j > 511) j = 511;
    return cx(j);
}
constexpr double csqrt(double v) {
    double g = v < 1.0 ? 1.0 : v;
    for (int it = 0; it < 40; ++it) g = 0.5 * (g + v / g);
    return g;
}

constexpr Tables make_tables() {
    Tables T{};
    double dwd[NXD][4] = {};
    for (int p = 0; p < NXD; ++p) {
        int base = p < 510 ? p : 510;
        int i = base + 3;
        double x = cx(p);
        double N[4] = {1, 0, 0, 0};
        double left[4] = {}, right[4] = {};
        for (int j = 1; j <= 3; ++j) {
            left[j]  = x - cknot(i + 1 - j);
            right[j] = cknot(i + j) - x;
            double saved = 0;
            for (int r = 0; r < j; ++r) {
                double temp = N[r] / (right[r + 1] + left[j - r]);
                N[r]  = saved + right[r + 1] * temp;
                saved = left[j - r] * temp;
            }
            N[j] = saved;
        }
        for (int a = 0; a < 4; ++a) { dwd[p][a] = N[a]; T.dw[p][a] = (float)N[a]; }
    }
    double band[4][MDIM] = {};
    for (int p = 0; p < NXD; ++p) {
        int base = p < 510 ? p : 510;
        for (int a = 0; a < 4; ++a)
            for (int b = a; b < 4; ++b)
                band[b - a][base + a] += dwd[p][a] * dwd[p][b];
    }
    for (int r = 0; r < MDIM; ++r) band[0][r] += SREG;
    double Ld[MDIM] = {}, L1a[MDIM] = {}, L2a[MDIM] = {}, L3a[MDIM] = {};
    for (int i = 0; i < MDIM; ++i) {
        double l3 = 0, l2 = 0, l1 = 0;
        if (i >= 3) l3 = band[3][i - 3] / Ld[i - 3];
        if (i >= 2) {
            double s = band[2][i - 2];
            if (i >= 3) s -= l3 * L1a[i - 2];
            l2 = s / Ld[i - 2];
        }
        if (i >= 1) {
            double s = band[1][i - 1];
            if (i >= 2) s -= l2 * L1a[i - 1];
            if (i >= 3) s -= l3 * L2a[i - 1];
            l1 = s / Ld[i - 1];
        }
        double s = band[0][i] - l1 * l1 - l2 * l2 - l3 * l3;
        Ld[i] = csqrt(s);
        L1a[i] = l1; L2a[i] = l2; L3a[i] = l3;
    }
    for (int j = 0; j < MDIM; ++j) {
        double dinv = 1.0 / Ld[j];
        T.bd[j] = (float)dinv;
        T.f1[j] = (float)(L1a[j] * dinv);
        T.f2[j] = (float)(L2a[j] * dinv);
        T.f3[j] = (float)(L3a[j] * dinv);
        T.g1[j] = (float)((j + 1 < MDIM ? L1a[j + 1] : 0.0) * dinv);
        T.g2[j] = (float)((j + 2 < MDIM ? L2a[j + 2] : 0.0) * dinv);
        T.g3[j] = (float)((j + 3 < MDIM ? L3a[j + 3] : 0.0) * dinv);
    }
    return T;
}

__device__ const Tables g_tab = make_tables();

// Scratch (device globals; allocation is forbidden)
__device__ float g_btz[MDIM][NROWS];     // B^T z, transposed
__device__ float g_ainv[MDIM][AROW];     // truncated A^-1 band, row i: taps i-W..i+W
__device__ float g_coef[MDIM][NROWS];    // solved coefficients

// ---------------------------------------------------------------------------
// K1: blocks 0..15 -> Btz (16 rows each); blocks 16..32 -> A^-1 band prep.
// ---------------------------------------------------------------------------
__global__ void __launch_bounds__(512) k1(const float* __restrict__ Z) {
    int b = blockIdx.x;
    int tid = threadIdx.x;

    if (b < 16) {
        __shared__ float s_z[16][513];
        int rowbase = b * 16;
        for (int idx = tid; idx < 16 * 512; idx += 512) {
            int r = idx >> 9, p = idx & 511;
            s_z[r][p] = Z[(size_t)(rowbase + r) * NXD + p];
        }
        __syncthreads();

        int w = tid >> 5, lane = tid & 31;
        int r = lane & 15, jg = lane >> 4;
#pragma unroll 1
        for (int s = 0; s < 17; ++s) {
            int j = w + 16 * jg + 32 * s;
            if (j >= MDIM) break;
            float acc = 0.f;
            int plo = j - 3 < 0 ? 0 : j - 3;
            int phi = j < 511 ? j : 511;
            for (int p = plo; p <= phi; ++p) {
                int base = p < 510 ? p : 510;
                int a = j - base;
                if (a >= 0 && a < 4) acc += g_tab.dw[p][a] * s_z[r][p];
            }
            g_btz[j][rowbase + r] = acc;
        }
    } else {
        // A^-1 band: column i, truncated to i +/- W
        int i = (b - 16) * 32 + tid;
        if (tid < 32 && i < MDIM) {
            float y[W + 1];
#pragma unroll
            for (int d = 0; d <= W; ++d) {
                int j = i + d;
                float v = 0.f;
                if (j < MDIM) {
                    if (d == 0) v = g_tab.bd[i];
                    else {
                        v = -g_tab.f1[j] * y[d - 1];
                        if (d >= 2) v = fmaf(-g_tab.f2[j], y[d - 2], v);
                        if (d >= 3) v = fmaf(-g_tab.f3[j], y[d - 3], v);
                    }
                }
                y[d] = v;
            }
            float c1 = 0.f, c2 = 0.f, c3 = 0.f;
#pragma unroll
            for (int dd = 0; dd <= 2 * W; ++dd) {
                int j = i + W - dd;
                float c = 0.f;
                if (j >= 0 && j < MDIM) {
                    float yv = (dd <= W) ? y[W - dd] : 0.f;
                    c = g_tab.bd[j] * yv;
                    c = fmaf(-g_tab.g1[j], c1, c);
                    c = fmaf(-g_tab.g2[j], c2, c);
                    c = fmaf(-g_tab.g3[j], c3, c);
                }
                g_ainv[i][2 * W - dd] = c;
                c3 = c2; c2 = c1; c1 = c;
            }
        }
    }
}

// ---------------------------------------------------------------------------
// K1b: coef = A^-1(band) * btz, computed once.
// grid (65 j-tiles of 8, 4 r-chunks of 64), 256 threads = 64 r x 4 j-slots.
// All hot loads are SMEM (s_a broadcast, s_b stride-1).
// ---------------------------------------------------------------------------
#define JT    8                       // j per tile
#define RC    64                      // rows per block
#define BW    (JT + 2 * W)            // 104 btz rows needed

__global__ void __launch_bounds__(256) k1b() {
    __shared__ float s_b[BW][RC];
    __shared__ float s_a[JT][NTAP + 1];
    int tid = threadIdx.x;
    int j0 = blockIdx.x * JT;
    int rbase = blockIdx.y * RC;
    int jb = j0 - W;

    for (int idx = tid; idx < BW * RC; idx += 256) {
        int jl = idx >> 6, r = idx & 63;
        int j = jb + jl;
        s_b[jl][r] = (j >= 0 && j < MDIM) ? g_btz[j][rbase + r] : 0.f;
    }
    for (int idx = tid; idx < JT * NTAP; idx += 256) {
        int jj = idx / NTAP, t = idx % NTAP;
        int j = j0 + jj;
        s_a[jj][t] = (j < MDIM) ? g_ainv[j][t] : 0.f;
    }
    __syncthreads();

    int r = tid & 63;
    int slot = tid >> 6;               // 0..3
    int jj0 = slot, jj1 = slot + 4;    // two j's per thread (ILP 2)
    float a0 = 0.f, a1 = 0.f;
#pragma unroll 4
    for (int t = 0; t < NTAP; ++t) {
        a0 = fmaf(s_a[jj0][t], s_b[jj0 + t][r], a0);
        a1 = fmaf(s_a[jj1][t], s_b[jj1 + t][r], a1);
    }
    int ja = j0 + jj0, jbn = j0 + jj1;
    if (ja < MDIM)  g_coef[ja][rbase + r]  = a0;
    if (jbn < MDIM) g_coef[jbn][rbase + r] = a1;
}

// ---------------------------------------------------------------------------
// K2: evaluation only. grid (32 e-chunks of 256, 16 r-chunks of 16),
// 128 threads = 64 e-groups (4 e each) x 2 row-halves (8 rows each).
// ---------------------------------------------------------------------------
#define EPB   256
#define RPB   16
#define JWIN  24

__device__ __forceinline__ float kf(int i) {
    int j = i - 3;
    j = j < 0 ? 0 : (j > 511 ? 511 : j);
    return (float)(-1.0 + 2.0 * (double)j / 511.0);
}

__device__ __forceinline__ int ebase_of(int e) {
    double x = -1.0 + 2.0 * (double)e / 8191.0;
    float xf = (float)x;
    int id = (int)floor(((double)xf + 1.0) * 255.5);
    return id < 0 ? 0 : (id > 510 ? 510 : id);
}

__device__ __forceinline__ void ewts(int e, float4& wout, int& idx) {
    float x = (float)(-1.0 + 2.0 * (double)e / 8191.0);
    int id = (int)floor(((double)x + 1.0) * 255.5);
    id = id < 0 ? 0 : (id > 510 ? 510 : id);
    int i = id + 3;
    float N[4] = {1.f, 0.f, 0.f, 0.f};
    float left[4], right[4];
#pragma unroll
    for (int j = 1; j <= 3; ++j) {
        left[j]  = x - kf(i + 1 - j);
        right[j] = kf(i + j) - x;
        float saved = 0.f;
#pragma unroll
        for (int r = 0; r < 3; ++r) {
            if (r < j) {
                float temp = __fdividef(N[r], right[r + 1] + left[j - r]);
                N[r]  = fmaf(right[r + 1], temp, saved);
                saved = left[j - r] * temp;
            }
        }
        N[j] = saved;
    }
    idx = id;
    wout = make_float4(N[0], N[1], N[2], N[3]);
}

__device__ __forceinline__ float ev4(float4 w, int o,
                                     float c0, float c1, float c2,
                                     float c3, float c4) {
    float a0 = o ? c1 : c0;
    float a1 = o ? c2 : c1;
    float a2 = o ? c3 : c2;
    float a3 = o ? c4 : c3;
    float v = w.x * a0;
    v = fmaf(w.y, a1, v);
    v = fmaf(w.z, a2, v);
    v = fmaf(w.w, a3, v);
    return v;
}

__global__ void __launch_bounds__(128) k2(float* __restrict__ out) {
    __shared__ float s_coef[JWIN][RPB];
    int tid = threadIdx.x;
    int e0 = blockIdx.x * EPB;
    int rbase = blockIdx.y * RPB;
    int j0 = ebase_of(e0);

    for (int idx = tid; idx < JWIN * RPB; idx += 128) {
        int jl = idx >> 4, r = idx & 15;
        int j = j0 + jl;
        if (j > MDIM - 1) j = MDIM - 1;
        s_coef[jl][r] = g_coef[j][rbase + r];
    }
    __syncthreads();

    int eg = tid & 63;
    int rh = tid >> 6;                 // 0/1
    int e = e0 + eg * 4;
    float4 w0, w1, w2, w3;
    int i0, i1, i2, i3;
    ewts(e,     w0, i0);
    ewts(e + 1, w1, i1);
    ewts(e + 2, w2, i2);
    ewts(e + 3, w3, i3);
    int b0 = i0 - j0;
    int o1 = i1 - i0;
    int o2 = i2 - i0;
    int o3 = i3 - i0;

    float4* outv = (float4*)(out + e);
#pragma unroll
    for (int rr = 0; rr < 8; ++rr) {
        int rl = rh * 8 + rr;
        int row = rbase + rl;
        const float* cp = &s_coef[b0][rl];
        float c0 = cp[0 * RPB];
        float c1 = cp[1 * RPB];
        float c2 = cp[2 * RPB];
        float c3 = cp[3 * RPB];
        float c4 = cp[4 * RPB];
        float4 v;
        v.x = w0.x * c0;
        v.x = fmaf(w0.y, c1, v.x);
        v.x = fmaf(w0.z, c2, v.x);
        v.x = fmaf(w0.w, c3, v.x);
        v.y = ev4(w1, o1, c0, c1, c2, c3, c4);
        v.z = ev4(w2, o2, c0, c1, c2, c3, c4);
        v.w = ev4(w3, o3, c0, c1, c2, c3, c4);
        outv[(size_t)row * (NEV / 4)] = v;
    }
}

// ---------------------------------------------------------------------------
extern "C" void kernel_launch(void* const* d_in, const int* in_sizes, int n_in,
                              void* d_out, int out_size) {
    const float* Z = (const float*)d_in[0];
    float* out = (float*)d_out;
    k1<<<33, 512>>>(Z);
    k1b<<<dim3((MDIM + JT - 1) / JT, NROWS / RC), 256>>>();
    k2<<<dim3(NEV / EPB, NROWS / RPB), 128>>>(out);
}

// round 5
// speedup vs baseline: 8.6626x; 1.4724x over previous
#include <cuda_runtime.h>
#include <math.h>

// Problem constants (fixed by dataset)
#define NXD   512          // design points
#define MDIM  514          // number of basis functions = NXD + 2 (k=3)
#define NEV   8192         // eval bins
#define NROWS 256          // 8*32 rows
#define SREG  1e-3

#define W     48           // inverse-band half-width used for truncation
#define D     56           // per-column inverse computation window
#define PB    100          // taps per M row: p in [j-51, j+48]

// ---------------------------------------------------------------------------
// Compile-time: M = A^-1(banded) * B^T, the full fit operator.
// coef[j] = sum_t M[j][t] * z[pstart(j)+t],  pstart(j) = max(0, j-51)
// ---------------------------------------------------------------------------
struct MBTab { float mb[MDIM][PB]; };

constexpr double cx(int i) { return -1.0 + 2.0 * (double)i / 511.0; }
constexpr double cknot(int i) {
    int j = i - 3;
    if (j < 0) j = 0;
    if (j > 511) j = 511;
    return cx(j);
}
constexpr double csqrt(double v) {
    double g = v < 1.0 ? 1.0 : v;
    for (int it = 0; it < 40; ++it) g = 0.5 * (g + v / g);
    return g;
}

constexpr MBTab make_mb() {
    MBTab T{};
    // design basis (Cox-de Boor, 4 nonzeros per point)
    double dwd[NXD][4] = {};
    for (int p = 0; p < NXD; ++p) {
        int base = p < 510 ? p : 510;
        int i = base + 3;
        double x = cx(p);
        double N[4] = {1, 0, 0, 0};
        double left[4] = {}, right[4] = {};
        for (int j = 1; j <= 3; ++j) {
            left[j]  = x - cknot(i + 1 - j);
            right[j] = cknot(i + j) - x;
            double saved = 0;
            for (int r = 0; r < j; ++r) {
                double temp = N[r] / (right[r + 1] + left[j - r]);
                N[r]  = saved + right[r + 1] * temp;
                saved = left[j - r] * temp;
            }
            N[j] = saved;
        }
        for (int a = 0; a < 4; ++a) dwd[p][a] = N[a];
    }
    // BtB band + regularization
    double band[4][MDIM] = {};
    for (int p = 0; p < NXD; ++p) {
        int base = p < 510 ? p : 510;
        for (int a = 0; a < 4; ++a)
            for (int b = a; b < 4; ++b)
                band[b - a][base + a] += dwd[p][a] * dwd[p][b];
    }
    for (int r = 0; r < MDIM; ++r) band[0][r] += SREG;
    // banded Cholesky (lower, bw 3): Ld diag, Lka[i] = L[i][i-k]
    double Ld[MDIM] = {}, L1a[MDIM] = {}, L2a[MDIM] = {}, L3a[MDIM] = {};
    for (int i = 0; i < MDIM; ++i) {
        double l3 = 0, l2 = 0, l1 = 0;
        if (i >= 3) l3 = band[3][i - 3] / Ld[i - 3];
        if (i >= 2) {
            double s = band[2][i - 2];
            if (i >= 3) s -= l3 * L1a[i - 2];
            l2 = s / Ld[i - 2];
        }
        if (i >= 1) {
            double s = band[1][i - 1];
            if (i >= 2) s -= l2 * L1a[i - 1];
            if (i >= 3) s -= l3 * L2a[i - 1];
            l1 = s / Ld[i - 1];
        }
        double s = band[0][i] - l1 * l1 - l2 * l2 - l3 * l3;
        Ld[i] = csqrt(s);
        L1a[i] = l1; L2a[i] = l2; L3a[i] = l3;
    }
    // per column j: c[jj] = A^-1[jj][j] within |jj-j| <= D, then fold with B^T
    for (int j = 0; j < MDIM; ++j) {
        double yw[D + 1] = {};
        yw[0] = 1.0 / Ld[j];
        for (int d = 1; d <= D; ++d) {
            int jj = j + d;
            if (jj < MDIM) {
                double s = -(L1a[jj] * yw[d - 1]);
                if (d >= 2) s -= L2a[jj] * yw[d - 2];
                if (d >= 3) s -= L3a[jj] * yw[d - 3];
                yw[d] = s / Ld[jj];
            }
        }
        double cw[2 * D + 4] = {};
        for (int s = 2 * D; s >= 0; --s) {
            int jj = j - D + s;
            if (jj >= 0 && jj < MDIM) {
                double yv = (s >= D) ? yw[s - D] : 0.0;
                double c = yv;
                c -= (jj + 1 < MDIM ? L1a[jj + 1] : 0.0) * cw[s + 1];
                c -= (jj + 2 < MDIM ? L2a[jj + 2] : 0.0) * cw[s + 2];
                c -= (jj + 3 < MDIM ? L3a[jj + 3] : 0.0) * cw[s + 3];
                cw[s] = c / Ld[jj];
            }
        }
        int ps = j - 51; if (ps < 0) ps = 0;
        int pe = j + W;  if (pe > 511) pe = 511;
        for (int t = 0; t < PB; ++t) {
            int p = ps + t;
            double sum = 0.0;
            if (p <= pe) {
                int base = p < 510 ? p : 510;
                for (int a = 0; a < 4; ++a) {
                    int jj = base + a;
                    int s = jj - (j - D);
                    if (s >= 0 && s <= 2 * D) sum += dwd[p][a] * cw[s];
                }
            }
            T.mb[j][t] = (float)sum;
        }
    }
    return T;
}

__device__ const MBTab g_mb = make_mb();

// Scratch (device globals; allocation is forbidden)
__device__ float g_coef[MDIM][NROWS];

// ---------------------------------------------------------------------------
// KA: coef = M * z.  grid (65 j-tiles of 8, 4 r-chunks of 64), 256 threads.
// ---------------------------------------------------------------------------
#define JT    8
#define RC    64
#define ZW    107
#define ZS    (RC + 1)     // padded row stride

__global__ void __launch_bounds__(256) kA(const float* __restrict__ Z) {
    __shared__ float s_z[ZW * ZS];
    __shared__ float s_m[JT][PB];
    int tid = threadIdx.x;
    int j0 = blockIdx.x * JT;
    int rbase = blockIdx.y * RC;
    int psBase = j0 - 51; if (psBase < 0) psBase = 0;

    // stage Z window: s_z[pp][r] (coalesced over p per Z row)
    for (int idx = tid; idx < ZW * RC; idx += 256) {
        int rr = idx / ZW, pp = idx % ZW;
        int p = psBase + pp;
        float v = 0.f;
        if (p < NXD) v = Z[(size_t)(rbase + rr) * NXD + p];
        s_z[pp * ZS + rr] = v;
    }
    // stage M tile
    for (int idx = tid; idx < JT * PB; idx += 256) {
        int jj = idx / PB, t = idx % PB;
        int j = j0 + jj;
        s_m[jj][t] = (j < MDIM) ? g_mb.mb[j][t] : 0.f;
    }
    __syncthreads();

    int r = tid & 63;
    int slot = tid >> 6;                // 0..3
    int jjA = slot, jjB = slot + 4;     // two j's per thread (ILP 2)
    int jA = j0 + jjA, jB = j0 + jjB;
    int zoA = (jA - 51 < 0 ? 0 : jA - 51) - psBase;
    int zoB = (jB - 51 < 0 ? 0 : jB - 51) - psBase;
    float a0 = 0.f, a1 = 0.f;
#pragma unroll 4
    for (int t = 0; t < PB; ++t) {
        a0 = fmaf(s_m[jjA][t], s_z[(zoA + t) * ZS + r], a0);
        a1 = fmaf(s_m[jjB][t], s_z[(zoB + t) * ZS + r], a1);
    }
    if (jA < MDIM) g_coef[jA][rbase + r] = a0;
    if (jB < MDIM) g_coef[jB][rbase + r] = a1;
}

// ---------------------------------------------------------------------------
// K2: evaluation. grid (32 e-chunks of 256, 16 r-chunks of 16), 128 threads.
// s_coef transposed [r][j] (conflict-free); uniform-B-spline weights interior.
// ---------------------------------------------------------------------------
#define EPB   256
#define RPB   16
#define JWIN  24
#define JS    28

__device__ __forceinline__ float kf(int i) {
    int j = i - 3;
    j = j < 0 ? 0 : (j > 511 ? 511 : j);
    return (float)(-1.0 + 2.0 * (double)j / 511.0);
}

__device__ __forceinline__ int ebase_of(int e) {
    double x = -1.0 + 2.0 * (double)e / 8191.0;
    float xf = (float)x;
    int id = (int)floor(((double)xf + 1.0) * 255.5);
    return id < 0 ? 0 : (id > 510 ? 510 : id);
}

// general fp32 De Boor (boundary intervals only)
__device__ __forceinline__ void ewts(int e, float4& wout, int& idx) {
    float x = (float)(-1.0 + 2.0 * (double)e / 8191.0);
    int id = ebase_of(e);
    int i = id + 3;
    float N[4] = {1.f, 0.f, 0.f, 0.f};
    float left[4], right[4];
#pragma unroll
    for (int j = 1; j <= 3; ++j) {
        left[j]  = x - kf(i + 1 - j);
        right[j] = kf(i + j) - x;
        float saved = 0.f;
#pragma unroll
        for (int r = 0; r < 3; ++r) {
            if (r < j) {
                float temp = __fdividef(N[r], right[r + 1] + left[j - r]);
                N[r]  = fmaf(right[r + 1], temp, saved);
                saved = left[j - r] * temp;
            }
        }
        N[j] = saved;
    }
    idx = id;
    wout = make_float4(N[0], N[1], N[2], N[3]);
}

__device__ __forceinline__ void weights(int e, float4& w, int& idx) {
    int prod = e * 511;
    int id = prod / 8191;
    if (id > 510) id = 510;
    if (id >= 3 && id <= 507) {
        float u = (float)(prod - id * 8191) * (1.0f / 8191.0f);
        float um = 1.f - u;
        float u2 = u * u, um2 = um * um;
        w.x = um2 * um * (1.f / 6.f);
        w.w = u2 * u * (1.f / 6.f);
        w.y = fmaf(3.f * u, u2, fmaf(-6.f, u2, 4.f)) * (1.f / 6.f);
        w.z = 1.f - w.x - w.y - w.w;
        idx = id;
    } else {
        ewts(e, w, idx);
    }
}

__global__ void __launch_bounds__(128) k2(float* __restrict__ out) {
    __shared__ float s_coef[RPB][JS];
    int tid = threadIdx.x;
    int e0 = blockIdx.x * EPB;
    int rbase = blockIdx.y * RPB;
    int j0a = ebase_of(e0);
    int j0b = e0 * 511 / 8191; if (j0b > 510) j0b = 510;
    int j0 = j0a < j0b ? j0a : j0b;

    for (int idx = tid; idx < JWIN * RPB; idx += 128) {
        int r = idx & 15, jl = idx >> 4;
        int j = j0 + jl;
        if (j > MDIM - 1) j = MDIM - 1;
        s_coef[r][jl] = g_coef[j][rbase + r];
    }
    __syncthreads();

    int eg = tid & 63;
    int rh = tid >> 6;
    int e = e0 + eg * 4;
    float4 w0, w1, w2, w3;
    int i0, i1, i2, i3;
    weights(e,     w0, i0);
    weights(e + 1, w1, i1);
    weights(e + 2, w2, i2);
    weights(e + 3, w3, i3);
    int b0 = i0 - j0, b1 = i1 - j0, b2 = i2 - j0, b3 = i3 - j0;

    float4* outv = (float4*)(out + e);
#pragma unroll
    for (int rr = 0; rr < 8; ++rr) {
        int rl = rh * 8 + rr;
        int row = rbase + rl;
        const float* cr = s_coef[rl];
        float4 v;
        v.x = w0.x * cr[b0];
        v.x = fmaf(w0.y, cr[b0 + 1], v.x);
        v.x = fmaf(w0.z, cr[b0 + 2], v.x);
        v.x = fmaf(w0.w, cr[b0 + 3], v.x);
        v.y = w1.x * cr[b1];
        v.y = fmaf(w1.y, cr[b1 + 1], v.y);
        v.y = fmaf(w1.z, cr[b1 + 2], v.y);
        v.y = fmaf(w1.w, cr[b1 + 3], v.y);
        v.z = w2.x * cr[b2];
        v.z = fmaf(w2.y, cr[b2 + 1], v.z);
        v.z = fmaf(w2.z, cr[b2 + 2], v.z);
        v.z = fmaf(w2.w, cr[b2 + 3], v.z);
        v.w = w3.x * cr[b3];
        v.w = fmaf(w3.y, cr[b3 + 1], v.w);
        v.w = fmaf(w3.z, cr[b3 + 2], v.w);
        v.w = fmaf(w3.w, cr[b3 + 3], v.w);
        outv[(size_t)row * (NEV / 4)] = v;
    }
}

// ---------------------------------------------------------------------------
extern "C" void kernel_launch(void* const* d_in, const int* in_sizes, int n_in,
                              void* d_out, int out_size) {
    const float* Z = (const float*)d_in[0];
    float* out = (float*)d_out;
    kA<<<dim3((MDIM + JT - 1) / JT, NROWS / RC), 256>>>(Z);
    k2<<<dim3(NEV / EPB, NROWS / RPB), 128>>>(out);
}